// round 5
// baseline (speedup 1.0000x reference)
#include <cuda_runtime.h>

// ConformalMetric: R = -2*exp(-2*Phi) * (lap(Phi) + 2*|grad(Phi)|^2)
// Phi = phi_pos - lambda*phi_neg, edge-clamped 6-point stencil, h=1.
// Shape (B,H,W,D) = (4,128,128,128), D contiguous.
//
// Round-5: barrier-free H-march, 2 planes per iteration -> 12 independent
// LDG.128 front-batched per step (2x MLP vs round 4). Packed f32x2 math.
// launch_bounds(256,4) gives ptxas ~64 regs to hold the load window.

#define Bn 4
#define Hn 128
#define Wn 128
#define Dn 128
#define WSLAB 8     // W rows per block
#define CH 4        // H planes per block (2 iterations of 2 planes)

typedef unsigned long long u64;

__device__ __forceinline__ u64 pk2(float lo, float hi) {
    u64 r; asm("mov.b64 %0, {%1, %2};" : "=l"(r) : "f"(lo), "f"(hi)); return r;
}
__device__ __forceinline__ void upk2(u64 v, float& lo, float& hi) {
    asm("mov.b64 {%0, %1}, %2;" : "=f"(lo), "=f"(hi) : "l"(v));
}
__device__ __forceinline__ u64 fma2(u64 a, u64 b, u64 c) {
    u64 r; asm("fma.rn.f32x2 %0, %1, %2, %3;" : "=l"(r) : "l"(a), "l"(b), "l"(c)); return r;
}
__device__ __forceinline__ u64 add2(u64 a, u64 b) {
    u64 r; asm("add.rn.f32x2 %0, %1, %2;" : "=l"(r) : "l"(a), "l"(b)); return r;
}
__device__ __forceinline__ u64 mul2(u64 a, u64 b) {
    u64 r; asm("mul.rn.f32x2 %0, %1, %2;" : "=l"(r) : "l"(a), "l"(b)); return r;
}
__device__ __forceinline__ float ex2f(float x) {
    float r; asm("ex2.approx.f32 %0, %1;" : "=f"(r) : "f"(x)); return r;
}

struct P4 { u64 lo, hi; };   // 4 floats as two packed f32x2

__global__ __launch_bounds__(256, 4) void conformal_pk2(
    const float* __restrict__ pos,
    const float* __restrict__ neg,
    const float* __restrict__ lam_p,
    float* __restrict__ out)
{
    const float lam = __ldg(lam_p);
    const u64 NEGLAM = pk2(-lam, -lam);
    const u64 NEG1   = pk2(-1.0f, -1.0f);
    const u64 NEG6   = pk2(-6.0f, -6.0f);
    const u64 HALF   = pk2(0.5f, 0.5f);
    const u64 N2L2E  = pk2(-2.8853900817779268f, -2.8853900817779268f); // -2*log2(e)
    const u64 NEG2   = pk2(-2.0f, -2.0f);

    const int tx = threadIdx.x;            // 0..31 -> d4 lane
    const int ty = threadIdx.y;            // 0..WSLAB-1 -> w row
    const int b  = blockIdx.z;
    const int h0 = blockIdx.y * CH;
    const int w  = blockIdx.x * WSLAB + ty;

    const int wm = (w > 0)      ? w - 1 : 0;
    const int wp = (w < Wn - 1) ? w + 1 : Wn - 1;

    const int base_b = b * Hn * Wn * Dn;
    const int dofs   = tx * 4;

    auto ldphi = [&](int hh, int ww) -> P4 {
        const int i = base_b + (hh * Wn + ww) * Dn + dofs;
        const ulonglong2 P = *reinterpret_cast<const ulonglong2*>(pos + i);
        const ulonglong2 N = *reinterpret_cast<const ulonglong2*>(neg + i);
        P4 r;
        r.lo = fma2(N.x, NEGLAM, P.x);     // phi = pos - lam*neg (packed)
        r.hi = fma2(N.y, NEGLAM, P.y);
        return r;
    };

    // stencil eval for one plane: Cc center, Cm/Cp H-neighbors, YM/YP W-neighbors
    auto evalR = [&](const P4& Cm, const P4& Cc, const P4& Cp,
                     const P4& YM, const P4& YP, int h) {
        float cx, cy, cz, cw;
        upk2(Cc.lo, cx, cy);
        upk2(Cc.hi, cz, cw);

        float zm0 = __shfl_up_sync(0xffffffffu,  cw, 1);
        float zp3 = __shfl_down_sync(0xffffffffu, cx, 1);
        if (tx == 0)  zm0 = cx;   // clamp d=0
        if (tx == 31) zp3 = cw;   // clamp d=Dn-1

        const u64 zm_lo = pk2(zm0, cx);
        const u64 mid   = pk2(cy, cz);     // zm.hi == zp.lo
        const u64 zp_hi = pk2(cw, zp3);

        float r0, r1, r2, r3;
#pragma unroll
        for (int half = 0; half < 2; ++half) {
            const u64 c  = half ? Cc.hi : Cc.lo;
            const u64 xm = half ? Cm.hi : Cm.lo;
            const u64 xp = half ? Cp.hi : Cp.lo;
            const u64 ym = half ? YM.hi : YM.lo;
            const u64 yp = half ? YP.hi : YP.lo;
            const u64 zm = half ? mid   : zm_lo;
            const u64 zp = half ? zp_hi : mid;

            const u64 dx = fma2(xm, NEG1, xp);           // xp - xm
            const u64 dy = fma2(ym, NEG1, yp);
            const u64 dz = fma2(zm, NEG1, zp);
            u64 sq = mul2(dz, dz);
            sq = fma2(dy, dy, sq);
            sq = fma2(dx, dx, sq);                       // sum d^2 = 4*grad_sq

            u64 lap = add2(add2(add2(xp, xm), add2(yp, ym)), add2(zp, zm));
            lap = fma2(c, NEG6, lap);                    // - 6c
            const u64 arg  = fma2(sq, HALF, lap);        // lap + 2*grad_sq
            const u64 m    = mul2(c, N2L2E);             // -2c*log2(e)
            const u64 narg = mul2(arg, NEG2);            // -2*arg

            float m0, m1, a0, a1;
            upk2(m, m0, m1);
            upk2(narg, a0, a1);
            const float e0 = ex2f(m0);                   // exp(-2c)
            const float e1 = ex2f(m1);
            if (half) { r2 = e0 * a0; r3 = e1 * a1; }
            else      { r0 = e0 * a0; r1 = e1 * a1; }
        }

        const int oidx = base_b + (h * Wn + w) * Dn + dofs;
        __stcs(reinterpret_cast<float4*>(out + oidx),
               make_float4(r0, r1, r2, r3));
    };

    // prologue: Phi(h0-1), Phi(h0)
    const int hm0 = (h0 > 0) ? h0 - 1 : 0;
    P4 Cm = ldphi(hm0, w);
    P4 Cc = ldphi(h0,  w);

#pragma unroll
    for (int hh = 0; hh < CH; hh += 2) {
        const int h1  = h0 + hh;
        const int h2  = h1 + 1;                          // < Hn (CH divides Hn)
        const int hp2 = (h2 < Hn - 1) ? h2 + 1 : Hn - 1;

        // 6 independent plane loads = 12 LDG.128 front-batched
        P4 Cp1 = ldphi(h2,  w);    // Phi(h1+1, w)
        P4 Cp2 = ldphi(hp2, w);    // Phi(h2+1, w)
        P4 YM1 = ldphi(h1, wm);
        P4 YP1 = ldphi(h1, wp);
        P4 YM2 = ldphi(h2, wm);
        P4 YP2 = ldphi(h2, wp);

        evalR(Cm,  Cc,  Cp1, YM1, YP1, h1);
        evalR(Cc,  Cp1, Cp2, YM2, YP2, h2);

        Cm = Cp1; Cc = Cp2;
    }
}

extern "C" void kernel_launch(void* const* d_in, const int* in_sizes, int n_in,
                              void* d_out, int out_size)
{
    const float* pos = (const float*)d_in[0];  // phi_positive (B,H,W,D) f32
    const float* neg = (const float*)d_in[1];  // phi_negative (B,H,W,D) f32
    const float* lam = (const float*)d_in[2];  // lambda_repulsion (1,) f32
    float* out = (float*)d_out;

    dim3 block(32, WSLAB, 1);                   // 256 threads
    dim3 grid(Wn / WSLAB, Hn / CH, Bn);         // (16, 32, 4) = 2048 blocks
    conformal_pk2<<<grid, block>>>(pos, neg, lam, out);
}